// round 6
// baseline (speedup 1.0000x reference)
#include <cuda_runtime.h>
#include <cuda_fp16.h>
#include <cstdint>

#define B_SAMPLES 32768
#define N_CLASSES 10
#define UNIT 16
#define D_IN 160
#define H1_DIM 512
#define H2_DIM 1024
#define O_DIM 3072

// quant scales (compile-time)
#define H2_CLAMP 0.5f
#define W3_BOUND 0.03125f   // 1/sqrt(1024)
#define H2_INVS (127.0f / H2_CLAMP)        // 254
#define W3_INVS (127.0f / W3_BOUND)        // 4064
#define DEQ3 ((H2_CLAMP / 127.0f) * (W3_BOUND / 127.0f))

// ---------------- scratch ----------------
__device__ __align__(128) __half g_vj[(size_t)B_SAMPLES * D_IN];
__device__ __align__(128) __half g_h1[(size_t)B_SAMPLES * H1_DIM];
__device__ __align__(128) int8_t g_h2q[(size_t)B_SAMPLES * H2_DIM];
__device__ __align__(128) __half g_w1[(size_t)D_IN * H1_DIM];
__device__ __align__(128) __half g_w2[(size_t)H1_DIM * H2_DIM];
__device__ __align__(128) int8_t g_w3q[(size_t)O_DIM * H2_DIM];  // [N][K] transposed

// ---------------- fp32 -> fp16 ----------------
__global__ void f2h_kernel(const float2* __restrict__ src,
                           __half2* __restrict__ dst, int n2) {
    int i = blockIdx.x * blockDim.x + threadIdx.x;
    int stride = gridDim.x * blockDim.x;
    for (; i < n2; i += stride) {
        float2 v = src[i];
        dst[i] = __floats2half2_rn(v.x, v.y);
    }
}

// ---------------- W3 transpose + int8 quantize: [K,N] fp32 -> [N,K] s8 ------
__global__ void w3_quant_kernel(const float* __restrict__ W,
                                int8_t* __restrict__ Wq) {
    __shared__ float t[32][33];
    int n0 = blockIdx.x * 32, k0 = blockIdx.y * 32;
    int tx = threadIdx.x, ty = threadIdx.y;
#pragma unroll
    for (int i = ty; i < 32; i += 8)
        t[i][tx] = W[(size_t)(k0 + i) * O_DIM + n0 + tx];
    __syncthreads();
#pragma unroll
    for (int i = ty; i < 32; i += 8) {
        int q = __float2int_rn(t[tx][i] * W3_INVS);
        q = max(-127, min(127, q));
        Wq[(size_t)(n0 + i) * H2_DIM + k0 + tx] = (int8_t)q;
    }
}

// ---------------- capsule mask ----------------
__global__ __launch_bounds__(256) void mask_kernel(const float* __restrict__ x,
                                                   __half* __restrict__ vj) {
    __shared__ float xs[64 * 168];
    __shared__ int bi[64];
    const int b0 = blockIdx.x * 64;

    const float4* src = (const float4*)(x + (size_t)b0 * D_IN);
    for (int q = threadIdx.x; q < 64 * 40; q += 256) {
        int s = q / 40, f = q % 40;
        *(float4*)&xs[s * 168 + f * 4] = src[q];
    }
    __syncthreads();

    if (threadIdx.x < 64) {
        const float* r = &xs[threadIdx.x * 168];
        float best = -1.f;
        int bidx = 0;
#pragma unroll
        for (int c = 0; c < N_CLASSES; c++) {
            float s = 0.f;
#pragma unroll
            for (int j = 0; j < UNIT; j++) {
                float v = r[c * UNIT + j];
                s += v * v;
            }
            if (s > best) { best = s; bidx = c; }
        }
        bi[threadIdx.x] = bidx;
    }
    __syncthreads();

    uint4* dst = (uint4*)(vj + (size_t)b0 * D_IN);
    for (int q = threadIdx.x; q < 64 * 20; q += 256) {
        int s = q / 20, j = q % 20;
        uint4 v = make_uint4(0u, 0u, 0u, 0u);
        int c = j >> 1;
        if (c == bi[s]) {
            const float* p = &xs[s * 168 + c * UNIT + (j & 1) * 8];
            __half2 h0 = __floats2half2_rn(p[0], p[1]);
            __half2 h1 = __floats2half2_rn(p[2], p[3]);
            __half2 h2 = __floats2half2_rn(p[4], p[5]);
            __half2 h3 = __floats2half2_rn(p[6], p[7]);
            v.x = *(uint32_t*)&h0; v.y = *(uint32_t*)&h1;
            v.z = *(uint32_t*)&h2; v.w = *(uint32_t*)&h3;
        }
        dst[q] = v;
    }
}

// ---------------- mma helpers ----------------
__device__ __forceinline__ void ldm_x4(uint32_t& r0, uint32_t& r1,
                                       uint32_t& r2, uint32_t& r3,
                                       uint32_t addr) {
    asm volatile("ldmatrix.sync.aligned.m8n8.x4.shared.b16 {%0,%1,%2,%3}, [%4];\n"
                 : "=r"(r0), "=r"(r1), "=r"(r2), "=r"(r3)
                 : "r"(addr));
}

__device__ __forceinline__ void ldm_x4_t(uint32_t& r0, uint32_t& r1,
                                         uint32_t& r2, uint32_t& r3,
                                         uint32_t addr) {
    asm volatile("ldmatrix.sync.aligned.m8n8.x4.trans.shared.b16 {%0,%1,%2,%3}, [%4];\n"
                 : "=r"(r0), "=r"(r1), "=r"(r2), "=r"(r3)
                 : "r"(addr));
}

__device__ __forceinline__ void mma_f16(uint32_t* c, const uint32_t* a,
                                        const uint32_t* b) {
    asm volatile(
        "mma.sync.aligned.m16n8k16.row.col.f16.f16.f16.f16 "
        "{%0,%1}, {%2,%3,%4,%5}, {%6,%7}, {%0,%1};\n"
        : "+r"(c[0]), "+r"(c[1])
        : "r"(a[0]), "r"(a[1]), "r"(a[2]), "r"(a[3]), "r"(b[0]), "r"(b[1]));
}

__device__ __forceinline__ void mma_s8(int* c, const uint32_t* a,
                                       const uint32_t* b) {
    asm volatile(
        "mma.sync.aligned.m16n8k32.row.col.s32.s8.s8.s32 "
        "{%0,%1,%2,%3}, {%4,%5,%6,%7}, {%8,%9}, {%0,%1,%2,%3};\n"
        : "+r"(c[0]), "+r"(c[1]), "+r"(c[2]), "+r"(c[3])
        : "r"(a[0]), "r"(a[1]), "r"(a[2]), "r"(a[3]), "r"(b[0]), "r"(b[1]));
}

// ================= fp16 GEMM (layers 1 & 2) =================
// BM=128, BN=128, BK=32, 4-stage pipeline, 256 thr (8 warps 2x4).
// ACT 0: relu -> half out ; ACT 2: relu + int8 quantize -> s8 out
#define BK 32
#define A_LDS 40
#define B_LDS 136
#define STAGES 4
#define A_STG (128 * A_LDS)
#define B_STG (BK * B_LDS)
#define SMEM_BYTES (STAGES * (A_STG + B_STG) * 2)

__device__ __forceinline__ void ld_stage(uint32_t sA, uint32_t sB,
                                         const __half* __restrict__ A,
                                         const __half* __restrict__ Bm,
                                         int bm, int bn, int K, int N, int t,
                                         int tid) {
    const __half* Ag = A + (size_t)bm * K + t * BK;
    const __half* Bg = Bm + (size_t)t * BK * N + bn;
#pragma unroll
    for (int i = 0; i < 2; i++) {
        int q = tid + i * 256;
        int ar = q >> 2, ac = (q & 3) * 8;
        asm volatile("cp.async.cg.shared.global [%0], [%1], 16;" ::
                     "r"(sA + (uint32_t)(ar * A_LDS + ac) * 2u),
                     "l"(Ag + (size_t)ar * K + ac));
        int br = q >> 4, bc = (q & 15) * 8;
        asm volatile("cp.async.cg.shared.global [%0], [%1], 16;" ::
                     "r"(sB + (uint32_t)(br * B_LDS + bc) * 2u),
                     "l"(Bg + (size_t)br * N + bc));
    }
    asm volatile("cp.async.commit_group;" ::: "memory");
}

template <int ACT>
__global__ __launch_bounds__(256, 2) void gemm_kernel(
    const __half* __restrict__ A,
    const __half* __restrict__ Bm,
    const float* __restrict__ bias,
    void* __restrict__ Cout,
    int M, int N, int K) {
    extern __shared__ __half smem[];

    const int tid = threadIdx.x;
    const int warp = tid >> 5;
    const int lane = tid & 31;
    const int warpM = warp >> 2;
    const int warpN = warp & 3;
    const int bm = blockIdx.y * 128;
    const int bn = blockIdx.x * 128;

    const uint32_t sBase = (uint32_t)__cvta_generic_to_shared(smem);
    const uint32_t aBase = sBase;
    const uint32_t bBase = sBase + (uint32_t)STAGES * A_STG * 2u;

    uint32_t acc[4][4][2];
#pragma unroll
    for (int mt = 0; mt < 4; mt++)
#pragma unroll
        for (int nt = 0; nt < 4; nt++) {
            acc[mt][nt][0] = 0u;
            acc[mt][nt][1] = 0u;
        }

    const int T = K / BK;

#pragma unroll
    for (int t = 0; t < STAGES - 1; t++)
        ld_stage(aBase + (uint32_t)t * A_STG * 2u, bBase + (uint32_t)t * B_STG * 2u,
                 A, Bm, bm, bn, K, N, t, tid);

    for (int t = 0; t < T; t++) {
        asm volatile("cp.async.wait_group %0;" :: "n"(STAGES - 2) : "memory");
        __syncthreads();

        if (t + STAGES - 1 < T) {
            int sl = (t + STAGES - 1) & (STAGES - 1);
            ld_stage(aBase + (uint32_t)sl * A_STG * 2u,
                     bBase + (uint32_t)sl * B_STG * 2u,
                     A, Bm, bm, bn, K, N, t + STAGES - 1, tid);
        }

        const int s = t & (STAGES - 1);
        const uint32_t sA = aBase + (uint32_t)s * A_STG * 2u;
        const uint32_t sB = bBase + (uint32_t)s * B_STG * 2u;

#pragma unroll
        for (int kk = 0; kk < BK; kk += 16) {
            uint32_t a[4][4];
#pragma unroll
            for (int mt = 0; mt < 4; mt++) {
                int row = warpM * 64 + mt * 16 + (lane & 15);
                int col = kk + ((lane >> 4) << 3);
                ldm_x4(a[mt][0], a[mt][1], a[mt][2], a[mt][3],
                       sA + (uint32_t)(row * A_LDS + col) * 2u);
            }
            uint32_t b[4][2];
#pragma unroll
            for (int g = 0; g < 2; g++) {
                int row = kk + (lane & 15);
                int col = warpN * 32 + g * 16 + ((lane >> 4) << 3);
                uint32_t r0, r1, r2, r3;
                ldm_x4_t(r0, r1, r2, r3, sB + (uint32_t)(row * B_LDS + col) * 2u);
                b[2 * g][0] = r0; b[2 * g][1] = r1;
                b[2 * g + 1][0] = r2; b[2 * g + 1][1] = r3;
            }
#pragma unroll
            for (int mt = 0; mt < 4; mt++)
#pragma unroll
                for (int nt = 0; nt < 4; nt++)
                    mma_f16(acc[mt][nt], a[mt], b[nt]);
        }
        __syncthreads();
    }

    const int lr = lane >> 2;
    const int lc = (lane & 3) * 2;
#pragma unroll
    for (int mt = 0; mt < 4; mt++) {
#pragma unroll
        for (int nt = 0; nt < 4; nt++) {
            int row0 = bm + warpM * 64 + mt * 16 + lr;
            int col = bn + warpN * 32 + nt * 8 + lc;
            float bz0 = __ldg(bias + col);
            float bz1 = __ldg(bias + col + 1);
            float2 p0 = __half22float2(*(__half2*)&acc[mt][nt][0]);
            float2 p1 = __half22float2(*(__half2*)&acc[mt][nt][1]);
            float v00 = fmaxf(p0.x + bz0, 0.f);
            float v01 = fmaxf(p0.y + bz1, 0.f);
            float v10 = fmaxf(p1.x + bz0, 0.f);
            float v11 = fmaxf(p1.y + bz1, 0.f);
            if (ACT == 0) {
                __half* C = (__half*)Cout;
                *(__half2*)&C[(size_t)row0 * N + col] = __floats2half2_rn(v00, v01);
                *(__half2*)&C[(size_t)(row0 + 8) * N + col] = __floats2half2_rn(v10, v11);
            } else {
                int8_t* C = (int8_t*)Cout;
                int q00 = min(127, __float2int_rn(v00 * H2_INVS));
                int q01 = min(127, __float2int_rn(v01 * H2_INVS));
                int q10 = min(127, __float2int_rn(v10 * H2_INVS));
                int q11 = min(127, __float2int_rn(v11 * H2_INVS));
                *(char2*)&C[(size_t)row0 * N + col] = make_char2((char)q00, (char)q01);
                *(char2*)&C[(size_t)(row0 + 8) * N + col] = make_char2((char)q10, (char)q11);
            }
        }
    }
}

// ================= int8 GEMM (layer 3) =================
// BM=128, BN=128, BK=64 bytes, 4-stage pipeline. A row-major [M,K] s8,
// B transposed [N,K] s8 (k contiguous for both). Conflict-free LDS feeds.
#define QBK 64
#define QLD 80                       // row stride bytes (64 + 16 pad)
#define QSTG (128 * QLD)             // per-operand stage bytes
#define QSMEM (STAGES * 2 * QSTG)    // 81920

__device__ __forceinline__ void ld_stage_q(uint32_t sA, uint32_t sB,
                                           const int8_t* __restrict__ A,
                                           const int8_t* __restrict__ Bt,
                                           int bm, int bn, int t, int tid) {
    const int8_t* Ag = A + (size_t)bm * H2_DIM + t * QBK;
    const int8_t* Bg = Bt + (size_t)bn * H2_DIM + t * QBK;
#pragma unroll
    for (int i = 0; i < 2; i++) {
        int q = tid + i * 256;
        int r = q >> 2, c = (q & 3) * 16;
        asm volatile("cp.async.cg.shared.global [%0], [%1], 16;" ::
                     "r"(sA + (uint32_t)(r * QLD + c)),
                     "l"(Ag + (size_t)r * H2_DIM + c));
        asm volatile("cp.async.cg.shared.global [%0], [%1], 16;" ::
                     "r"(sB + (uint32_t)(r * QLD + c)),
                     "l"(Bg + (size_t)r * H2_DIM + c));
    }
    asm volatile("cp.async.commit_group;" ::: "memory");
}

__global__ __launch_bounds__(256, 2) void gemm3_s8(
    const int8_t* __restrict__ A,
    const int8_t* __restrict__ Bt,
    const float* __restrict__ bias,
    float* __restrict__ C) {
    extern __shared__ int8_t smem8[];

    const int tid = threadIdx.x;
    const int warp = tid >> 5;
    const int lane = tid & 31;
    const int warpM = warp >> 2;
    const int warpN = warp & 3;
    const int bm = blockIdx.y * 128;
    const int bn = blockIdx.x * 128;
    const int g = lane >> 2;
    const int tig = lane & 3;

    const uint32_t sBase = (uint32_t)__cvta_generic_to_shared(smem8);
    const uint32_t aBase = sBase;
    const uint32_t bBase = sBase + (uint32_t)STAGES * QSTG;

    int acc[4][4][4];
#pragma unroll
    for (int mt = 0; mt < 4; mt++)
#pragma unroll
        for (int nt = 0; nt < 4; nt++)
#pragma unroll
            for (int r = 0; r < 4; r++) acc[mt][nt][r] = 0;

    const int T = H2_DIM / QBK;  // 16

#pragma unroll
    for (int t = 0; t < STAGES - 1; t++)
        ld_stage_q(aBase + (uint32_t)t * QSTG, bBase + (uint32_t)t * QSTG,
                   A, Bt, bm, bn, t, tid);

    for (int t = 0; t < T; t++) {
        asm volatile("cp.async.wait_group %0;" :: "n"(STAGES - 2) : "memory");
        __syncthreads();

        if (t + STAGES - 1 < T) {
            int sl = (t + STAGES - 1) & (STAGES - 1);
            ld_stage_q(aBase + (uint32_t)sl * QSTG, bBase + (uint32_t)sl * QSTG,
                       A, Bt, bm, bn, t + STAGES - 1, tid);
        }

        const int s = t & (STAGES - 1);
        const int8_t* As = smem8 + (size_t)s * QSTG;
        const int8_t* Bs = smem8 + (size_t)STAGES * QSTG + (size_t)s * QSTG;

#pragma unroll
        for (int kk = 0; kk < QBK; kk += 32) {
            uint32_t a[4][4];
#pragma unroll
            for (int mt = 0; mt < 4; mt++) {
                const int8_t* p = As + (warpM * 64 + mt * 16 + g) * QLD + kk + tig * 4;
                a[mt][0] = *(const uint32_t*)p;
                a[mt][1] = *(const uint32_t*)(p + 8 * QLD);
                a[mt][2] = *(const uint32_t*)(p + 16);
                a[mt][3] = *(const uint32_t*)(p + 8 * QLD + 16);
            }
            uint32_t b[4][2];
#pragma unroll
            for (int nt = 0; nt < 4; nt++) {
                const int8_t* p = Bs + (warpN * 32 + nt * 8 + g) * QLD + kk + tig * 4;
                b[nt][0] = *(const uint32_t*)p;
                b[nt][1] = *(const uint32_t*)(p + 16);
            }
#pragma unroll
            for (int mt = 0; mt < 4; mt++)
#pragma unroll
                for (int nt = 0; nt < 4; nt++)
                    mma_s8(acc[mt][nt], a[mt], b[nt]);
        }
        __syncthreads();
    }

    // epilogue: dequant + bias + sigmoid
    const int lr = lane >> 2;
    const int lc = (lane & 3) * 2;
#pragma unroll
    for (int mt = 0; mt < 4; mt++) {
#pragma unroll
        for (int nt = 0; nt < 4; nt++) {
            int row0 = bm + warpM * 64 + mt * 16 + lr;
            int col = bn + warpN * 32 + nt * 8 + lc;
            float bz0 = __ldg(bias + col);
            float bz1 = __ldg(bias + col + 1);
            float z00 = (float)acc[mt][nt][0] * DEQ3 + bz0;
            float z01 = (float)acc[mt][nt][1] * DEQ3 + bz1;
            float z10 = (float)acc[mt][nt][2] * DEQ3 + bz0;
            float z11 = (float)acc[mt][nt][3] * DEQ3 + bz1;
            float v00 = 1.f / (1.f + __expf(-z00));
            float v01 = 1.f / (1.f + __expf(-z01));
            float v10 = 1.f / (1.f + __expf(-z10));
            float v11 = 1.f / (1.f + __expf(-z11));
            *(float2*)&C[(size_t)row0 * O_DIM + col] = make_float2(v00, v01);
            *(float2*)&C[(size_t)(row0 + 8) * O_DIM + col] = make_float2(v10, v11);
        }
    }
}

// ---------------- launch ----------------
extern "C" void kernel_launch(void* const* d_in, const int* in_sizes, int n_in,
                              void* d_out, int out_size) {
    const float* x  = (const float*)d_in[0];
    const float* W1 = (const float*)d_in[2];
    const float* b1 = (const float*)d_in[3];
    const float* W2 = (const float*)d_in[4];
    const float* b2 = (const float*)d_in[5];
    const float* W3 = (const float*)d_in[6];
    const float* b3 = (const float*)d_in[7];

    void *pvj, *ph1, *ph2, *pw1, *pw2, *pw3;
    cudaGetSymbolAddress(&pvj, g_vj);
    cudaGetSymbolAddress(&ph1, g_h1);
    cudaGetSymbolAddress(&ph2, g_h2q);
    cudaGetSymbolAddress(&pw1, g_w1);
    cudaGetSymbolAddress(&pw2, g_w2);
    cudaGetSymbolAddress(&pw3, g_w3q);
    __half* vj   = (__half*)pvj;
    __half* h1   = (__half*)ph1;
    int8_t* h2q  = (int8_t*)ph2;
    __half* w1h  = (__half*)pw1;
    __half* w2h  = (__half*)pw2;
    int8_t* w3q  = (int8_t*)pw3;

    cudaFuncSetAttribute(gemm_kernel<0>,
                         cudaFuncAttributeMaxDynamicSharedMemorySize, SMEM_BYTES);
    cudaFuncSetAttribute(gemm_kernel<2>,
                         cudaFuncAttributeMaxDynamicSharedMemorySize, SMEM_BYTES);
    cudaFuncSetAttribute(gemm3_s8,
                         cudaFuncAttributeMaxDynamicSharedMemorySize, QSMEM);

    f2h_kernel<<<128, 256>>>((const float2*)W1, (__half2*)w1h,
                             D_IN * H1_DIM / 2);
    f2h_kernel<<<256, 256>>>((const float2*)W2, (__half2*)w2h,
                             H1_DIM * H2_DIM / 2);
    w3_quant_kernel<<<dim3(O_DIM / 32, H2_DIM / 32), dim3(32, 8)>>>(W3, w3q);

    mask_kernel<<<B_SAMPLES / 64, 256>>>(x, vj);

    gemm_kernel<0><<<dim3(H1_DIM / 128, B_SAMPLES / 128), 256, SMEM_BYTES>>>(
        vj, w1h, b1, h1, B_SAMPLES, H1_DIM, D_IN);
    gemm_kernel<2><<<dim3(H2_DIM / 128, B_SAMPLES / 128), 256, SMEM_BYTES>>>(
        h1, w2h, b2, h2q, B_SAMPLES, H2_DIM, H1_DIM);
    gemm3_s8<<<dim3(O_DIM / 128, B_SAMPLES / 128), 256, QSMEM>>>(
        h2q, w3q, b3, (float*)d_out);
}

// round 7
// speedup vs baseline: 1.1571x; 1.1571x over previous
#include <cuda_runtime.h>
#include <cuda_fp16.h>
#include <cstdint>

#define B_SAMPLES 32768
#define M_PAD 32832            // 228 * 144
#define TILE_M 144             // 128 tensor rows + 16 fma rows
#define GRID_Y 228
#define N_CLASSES 10
#define UNIT 16
#define D_IN 160
#define H1_DIM 512
#define H2_DIM 1024
#define O_DIM 3072

// ---------------- scratch (padded to M_PAD rows) ----------------
__device__ __align__(128) __half g_vj[(size_t)M_PAD * D_IN];
__device__ __align__(128) __half g_h1[(size_t)M_PAD * H1_DIM];
__device__ __align__(128) __half g_h2[(size_t)M_PAD * H2_DIM];
__device__ __align__(128) __half g_w1[(size_t)D_IN * H1_DIM];
__device__ __align__(128) __half g_w2[(size_t)H1_DIM * H2_DIM];
__device__ __align__(128) __half g_w3[(size_t)H2_DIM * O_DIM];

// ---------------- fp32 -> fp16 ----------------
__global__ void f2h_kernel(const float2* __restrict__ src,
                           __half2* __restrict__ dst, int n2) {
    int i = blockIdx.x * blockDim.x + threadIdx.x;
    int stride = gridDim.x * blockDim.x;
    for (; i < n2; i += stride) {
        float2 v = src[i];
        dst[i] = __floats2half2_rn(v.x, v.y);
    }
}

// ---------------- capsule mask ----------------
__global__ __launch_bounds__(256) void mask_kernel(const float* __restrict__ x,
                                                   __half* __restrict__ vj) {
    __shared__ float xs[64 * 168];
    __shared__ int bi[64];
    const int b0 = blockIdx.x * 64;

    const float4* src = (const float4*)(x + (size_t)b0 * D_IN);
    for (int q = threadIdx.x; q < 64 * 40; q += 256) {
        int s = q / 40, f = q % 40;
        *(float4*)&xs[s * 168 + f * 4] = src[q];
    }
    __syncthreads();

    if (threadIdx.x < 64) {
        const float* r = &xs[threadIdx.x * 168];
        float best = -1.f;
        int bidx = 0;
#pragma unroll
        for (int c = 0; c < N_CLASSES; c++) {
            float s = 0.f;
#pragma unroll
            for (int j = 0; j < UNIT; j++) {
                float v = r[c * UNIT + j];
                s += v * v;
            }
            if (s > best) { best = s; bidx = c; }
        }
        bi[threadIdx.x] = bidx;
    }
    __syncthreads();

    uint4* dst = (uint4*)(vj + (size_t)b0 * D_IN);
    for (int q = threadIdx.x; q < 64 * 20; q += 256) {
        int s = q / 20, j = q % 20;
        uint4 v = make_uint4(0u, 0u, 0u, 0u);
        int c = j >> 1;
        if (c == bi[s]) {
            const float* p = &xs[s * 168 + c * UNIT + (j & 1) * 8];
            __half2 h0 = __floats2half2_rn(p[0], p[1]);
            __half2 h1 = __floats2half2_rn(p[2], p[3]);
            __half2 h2 = __floats2half2_rn(p[4], p[5]);
            __half2 h3 = __floats2half2_rn(p[6], p[7]);
            v.x = *(uint32_t*)&h0; v.y = *(uint32_t*)&h1;
            v.z = *(uint32_t*)&h2; v.w = *(uint32_t*)&h3;
        }
        dst[q] = v;
    }
}

// ---------------- mma helpers ----------------
__device__ __forceinline__ void ldm_x4(uint32_t& r0, uint32_t& r1,
                                       uint32_t& r2, uint32_t& r3,
                                       uint32_t addr) {
    asm volatile("ldmatrix.sync.aligned.m8n8.x4.shared.b16 {%0,%1,%2,%3}, [%4];\n"
                 : "=r"(r0), "=r"(r1), "=r"(r2), "=r"(r3)
                 : "r"(addr));
}

__device__ __forceinline__ void ldm_x4_t(uint32_t& r0, uint32_t& r1,
                                         uint32_t& r2, uint32_t& r3,
                                         uint32_t addr) {
    asm volatile("ldmatrix.sync.aligned.m8n8.x4.trans.shared.b16 {%0,%1,%2,%3}, [%4];\n"
                 : "=r"(r0), "=r"(r1), "=r"(r2), "=r"(r3)
                 : "r"(addr));
}

__device__ __forceinline__ void mma_f16(uint32_t* c, const uint32_t* a,
                                        const uint32_t* b) {
    asm volatile(
        "mma.sync.aligned.m16n8k16.row.col.f16.f16.f16.f16 "
        "{%0,%1}, {%2,%3,%4,%5}, {%6,%7}, {%0,%1};\n"
        : "+r"(c[0]), "+r"(c[1])
        : "r"(a[0]), "r"(a[1]), "r"(a[2]), "r"(a[3]), "r"(b[0]), "r"(b[1]));
}

// ---------------- geometry ----------------
#define BK 32
#define A_LDS 40     // 32 + 8 pad (halves)
#define B_LDS 136    // 128 + 8 pad (halves)
#define STAGES 4
#define A_STG (TILE_M * A_LDS)     // 5760 halves (144 rows)
#define B_STG (BK * B_LDS)         // 4352 halves
#define SMEM_BYTES (STAGES * (A_STG + B_STG) * 2)   // 80896 B

#define NTHREADS 384

// loads A tile 144x32 + B tile 32x128 for stage; all 384 threads participate
__device__ __forceinline__ void ld_stage(uint32_t sA, uint32_t sB,
                                         const __half* __restrict__ A,
                                         const __half* __restrict__ Bm,
                                         int bm, int bn, int K, int N, int t,
                                         int tid) {
    const __half* Ag = A + (size_t)bm * K + t * BK;
    const __half* Bg = Bm + (size_t)t * BK * N + bn;
    // A: 144*32/8 = 576 chunks of 16B
    {
        int q = tid;
        int r = q >> 2, c = (q & 3) * 8;
        asm volatile("cp.async.cg.shared.global [%0], [%1], 16;" ::
                     "r"(sA + (uint32_t)(r * A_LDS + c) * 2u),
                     "l"(Ag + (size_t)r * K + c));
        q = tid + NTHREADS;
        if (q < 576) {
            r = q >> 2; c = (q & 3) * 8;
            asm volatile("cp.async.cg.shared.global [%0], [%1], 16;" ::
                         "r"(sA + (uint32_t)(r * A_LDS + c) * 2u),
                         "l"(Ag + (size_t)r * K + c));
        }
    }
    // B: 32*128/8 = 512 chunks
    {
        int q = tid;
        int r = q >> 4, c = (q & 15) * 8;
        asm volatile("cp.async.cg.shared.global [%0], [%1], 16;" ::
                     "r"(sB + (uint32_t)(r * B_LDS + c) * 2u),
                     "l"(Bg + (size_t)r * N + c));
        q = tid + NTHREADS;
        if (q < 512) {
            r = q >> 4; c = (q & 15) * 8;
            asm volatile("cp.async.cg.shared.global [%0], [%1], 16;" ::
                         "r"(sB + (uint32_t)(r * B_LDS + c) * 2u),
                         "l"(Bg + (size_t)r * N + c));
        }
    }
    asm volatile("cp.async.commit_group;" ::: "memory");
}

// ================= hybrid GEMM: tile 144x128 =================
// warps 0-7: tensor core on rows [bm, bm+128) x 128 cols (R4 core).
// warps 8-11: HFMA2 on rows [bm+128, bm+144) x same 128 cols, same B tile.
// ACT 0: relu -> half ; ACT 1: sigmoid -> float
template <int ACT>
__global__ __launch_bounds__(NTHREADS, 2) void gemm_kernel(
    const __half* __restrict__ A,
    const __half* __restrict__ Bm,
    const float* __restrict__ bias,
    void* __restrict__ Cout,
    int N, int K) {
    extern __shared__ __half smem[];

    const int tid = threadIdx.x;
    const int warp = tid >> 5;
    const int lane = tid & 31;
    const int bm = blockIdx.y * TILE_M;
    const int bn = blockIdx.x * 128;

    const uint32_t sBase = (uint32_t)__cvta_generic_to_shared(smem);
    const uint32_t aBase = sBase;
    const uint32_t bBase = sBase + (uint32_t)STAGES * A_STG * 2u;

    const int T = K / BK;

    // accumulators (disjoint live ranges per warp role)
    uint32_t tacc[4][4][2];   // tensor: fp16x2 pairs
    float2 facc[4][2];        // fma: 4 rows x 4 cols

    const int warpM = warp >> 2;
    const int warpN = warp & 3;
    const int fw = warp - 8;

    if (warp < 8) {
#pragma unroll
        for (int mt = 0; mt < 4; mt++)
#pragma unroll
            for (int nt = 0; nt < 4; nt++) {
                tacc[mt][nt][0] = 0u;
                tacc[mt][nt][1] = 0u;
            }
    } else {
#pragma unroll
        for (int r = 0; r < 4; r++) {
            facc[r][0] = make_float2(0.f, 0.f);
            facc[r][1] = make_float2(0.f, 0.f);
        }
    }

#pragma unroll
    for (int t = 0; t < STAGES - 1; t++)
        ld_stage(aBase + (uint32_t)t * A_STG * 2u, bBase + (uint32_t)t * B_STG * 2u,
                 A, Bm, bm, bn, K, N, t, tid);

    for (int t = 0; t < T; t++) {
        asm volatile("cp.async.wait_group %0;" :: "n"(STAGES - 2) : "memory");
        __syncthreads();

        if (t + STAGES - 1 < T) {
            int sl = (t + STAGES - 1) & (STAGES - 1);
            ld_stage(aBase + (uint32_t)sl * A_STG * 2u,
                     bBase + (uint32_t)sl * B_STG * 2u,
                     A, Bm, bm, bn, K, N, t + STAGES - 1, tid);
        }

        const int s = t & (STAGES - 1);

        if (warp < 8) {
            // ---------- tensor warps ----------
            const uint32_t sA = aBase + (uint32_t)s * A_STG * 2u;
            const uint32_t sB = bBase + (uint32_t)s * B_STG * 2u;
#pragma unroll
            for (int kk = 0; kk < BK; kk += 16) {
                uint32_t a[4][4];
#pragma unroll
                for (int mt = 0; mt < 4; mt++) {
                    int row = warpM * 64 + mt * 16 + (lane & 15);
                    int col = kk + ((lane >> 4) << 3);
                    ldm_x4(a[mt][0], a[mt][1], a[mt][2], a[mt][3],
                           sA + (uint32_t)(row * A_LDS + col) * 2u);
                }
                uint32_t b[4][2];
#pragma unroll
                for (int g = 0; g < 2; g++) {
                    int row = kk + (lane & 15);
                    int col = warpN * 32 + g * 16 + ((lane >> 4) << 3);
                    uint32_t r0, r1, r2, r3;
                    ldm_x4_t(r0, r1, r2, r3,
                             sB + (uint32_t)(row * B_LDS + col) * 2u);
                    b[2 * g][0] = r0; b[2 * g][1] = r1;
                    b[2 * g + 1][0] = r2; b[2 * g + 1][1] = r3;
                }
#pragma unroll
                for (int mt = 0; mt < 4; mt++)
#pragma unroll
                    for (int nt = 0; nt < 4; nt++)
                        mma_f16(tacc[mt][nt], a[mt], b[nt]);
            }
        } else {
            // ---------- fma warps: rows 128+fw*4 .. +3, cols lane*4 .. +3 ----
            const __half* As = smem + (size_t)s * A_STG;
            const __half* Bs = smem + (size_t)STAGES * A_STG + (size_t)s * B_STG;
            const int rowb = 128 + fw * 4;
#pragma unroll
            for (int kc = 0; kc < BK; kc += 8) {
                uint4 a4[4];
#pragma unroll
                for (int r = 0; r < 4; r++)
                    a4[r] = *(const uint4*)&As[(rowb + r) * A_LDS + kc];
                __half2 ih[4][2];
#pragma unroll
                for (int r = 0; r < 4; r++) {
                    ih[r][0] = __floats2half2_rn(0.f, 0.f);
                    ih[r][1] = __floats2half2_rn(0.f, 0.f);
                }
#pragma unroll
                for (int kk = 0; kk < 8; kk++) {
                    uint2 b2 = *(const uint2*)&Bs[(kc + kk) * B_LDS + lane * 4];
                    __half2 b0 = *(__half2*)&b2.x;
                    __half2 b1 = *(__half2*)&b2.y;
#pragma unroll
                    for (int r = 0; r < 4; r++) {
                        __half av = ((const __half*)&a4[r])[kk];
                        __half2 av2 = __half2half2(av);
                        ih[r][0] = __hfma2(av2, b0, ih[r][0]);
                        ih[r][1] = __hfma2(av2, b1, ih[r][1]);
                    }
                }
#pragma unroll
                for (int r = 0; r < 4; r++) {
                    float2 f0 = __half22float2(ih[r][0]);
                    float2 f1 = __half22float2(ih[r][1]);
                    facc[r][0].x += f0.x; facc[r][0].y += f0.y;
                    facc[r][1].x += f1.x; facc[r][1].y += f1.y;
                }
            }
        }
        __syncthreads();
    }

    // ---------------- epilogues ----------------
    if (warp < 8) {
        const int lr = lane >> 2;
        const int lc = (lane & 3) * 2;
#pragma unroll
        for (int mt = 0; mt < 4; mt++) {
#pragma unroll
            for (int nt = 0; nt < 4; nt++) {
                int row0 = bm + warpM * 64 + mt * 16 + lr;
                int col = bn + warpN * 32 + nt * 8 + lc;
                float bz0 = __ldg(bias + col);
                float bz1 = __ldg(bias + col + 1);
                float2 p0 = __half22float2(*(__half2*)&tacc[mt][nt][0]);
                float2 p1 = __half22float2(*(__half2*)&tacc[mt][nt][1]);
                float v00 = p0.x + bz0;
                float v01 = p0.y + bz1;
                float v10 = p1.x + bz0;
                float v11 = p1.y + bz1;
                if (ACT == 0) {
                    v00 = fmaxf(v00, 0.f); v01 = fmaxf(v01, 0.f);
                    v10 = fmaxf(v10, 0.f); v11 = fmaxf(v11, 0.f);
                    __half* C = (__half*)Cout;
                    if (row0 < B_SAMPLES)
                        *(__half2*)&C[(size_t)row0 * N + col] =
                            __floats2half2_rn(v00, v01);
                    if (row0 + 8 < B_SAMPLES)
                        *(__half2*)&C[(size_t)(row0 + 8) * N + col] =
                            __floats2half2_rn(v10, v11);
                } else {
                    v00 = 1.f / (1.f + __expf(-v00));
                    v01 = 1.f / (1.f + __expf(-v01));
                    v10 = 1.f / (1.f + __expf(-v10));
                    v11 = 1.f / (1.f + __expf(-v11));
                    float* C = (float*)Cout;
                    if (row0 < B_SAMPLES)
                        *(float2*)&C[(size_t)row0 * N + col] = make_float2(v00, v01);
                    if (row0 + 8 < B_SAMPLES)
                        *(float2*)&C[(size_t)(row0 + 8) * N + col] = make_float2(v10, v11);
                }
            }
        }
    } else {
        const int col = bn + lane * 4;
        float4 bz = __ldg((const float4*)(bias + col));
#pragma unroll
        for (int r = 0; r < 4; r++) {
            int row = bm + 128 + fw * 4 + r;
            if (row >= B_SAMPLES) continue;
            float v0 = facc[r][0].x + bz.x;
            float v1 = facc[r][0].y + bz.y;
            float v2 = facc[r][1].x + bz.z;
            float v3 = facc[r][1].y + bz.w;
            if (ACT == 0) {
                v0 = fmaxf(v0, 0.f); v1 = fmaxf(v1, 0.f);
                v2 = fmaxf(v2, 0.f); v3 = fmaxf(v3, 0.f);
                __half* C = (__half*)Cout;
                __half2 h0 = __floats2half2_rn(v0, v1);
                __half2 h1 = __floats2half2_rn(v2, v3);
                uint2 pk;
                pk.x = *(uint32_t*)&h0;
                pk.y = *(uint32_t*)&h1;
                *(uint2*)&C[(size_t)row * N + col] = pk;
            } else {
                v0 = 1.f / (1.f + __expf(-v0));
                v1 = 1.f / (1.f + __expf(-v1));
                v2 = 1.f / (1.f + __expf(-v2));
                v3 = 1.f / (1.f + __expf(-v3));
                float* C = (float*)Cout;
                *(float4*)&C[(size_t)row * N + col] = make_float4(v0, v1, v2, v3);
            }
        }
    }
}

// ---------------- launch ----------------
extern "C" void kernel_launch(void* const* d_in, const int* in_sizes, int n_in,
                              void* d_out, int out_size) {
    const float* x  = (const float*)d_in[0];
    const float* W1 = (const float*)d_in[2];
    const float* b1 = (const float*)d_in[3];
    const float* W2 = (const float*)d_in[4];
    const float* b2 = (const float*)d_in[5];
    const float* W3 = (const float*)d_in[6];
    const float* b3 = (const float*)d_in[7];

    void *pvj, *ph1, *ph2, *pw1, *pw2, *pw3;
    cudaGetSymbolAddress(&pvj, g_vj);
    cudaGetSymbolAddress(&ph1, g_h1);
    cudaGetSymbolAddress(&ph2, g_h2);
    cudaGetSymbolAddress(&pw1, g_w1);
    cudaGetSymbolAddress(&pw2, g_w2);
    cudaGetSymbolAddress(&pw3, g_w3);
    __half* vj  = (__half*)pvj;
    __half* h1  = (__half*)ph1;
    __half* h2  = (__half*)ph2;
    __half* w1h = (__half*)pw1;
    __half* w2h = (__half*)pw2;
    __half* w3h = (__half*)pw3;

    cudaFuncSetAttribute(gemm_kernel<0>,
                         cudaFuncAttributeMaxDynamicSharedMemorySize, SMEM_BYTES);
    cudaFuncSetAttribute(gemm_kernel<1>,
                         cudaFuncAttributeMaxDynamicSharedMemorySize, SMEM_BYTES);

    f2h_kernel<<<128, 256>>>((const float2*)W1, (__half2*)w1h,
                             D_IN * H1_DIM / 2);
    f2h_kernel<<<256, 256>>>((const float2*)W2, (__half2*)w2h,
                             H1_DIM * H2_DIM / 2);
    f2h_kernel<<<512, 256>>>((const float2*)W3, (__half2*)w3h,
                             H2_DIM * O_DIM / 2);

    mask_kernel<<<B_SAMPLES / 64, 256>>>(x, vj);

    gemm_kernel<0><<<dim3(H1_DIM / 128, GRID_Y), NTHREADS, SMEM_BYTES>>>(
        vj, w1h, b1, h1, H1_DIM, D_IN);
    gemm_kernel<0><<<dim3(H2_DIM / 128, GRID_Y), NTHREADS, SMEM_BYTES>>>(
        h1, w2h, b2, h2, H2_DIM, H1_DIM);
    gemm_kernel<1><<<dim3(O_DIM / 128, GRID_Y), NTHREADS, SMEM_BYTES>>>(
        h2, w3h, b3, d_out, O_DIM, H2_DIM);
}

// round 8
// speedup vs baseline: 1.3974x; 1.2077x over previous
#include <cuda_runtime.h>
#include <cuda_fp16.h>
#include <cstdint>

#define B_SAMPLES 32768
#define TILE_M 136             // 128 tensor rows + 8 fma rows
#define GRID_Y 241             // ceil(32768/136)
#define M_PAD (GRID_Y * TILE_M)  // 32776
#define N_CLASSES 10
#define UNIT 16
#define D_IN 160
#define H1_DIM 512
#define H2_DIM 1024
#define O_DIM 3072

// ---------------- scratch (padded to M_PAD rows; pads stay zero) ------------
__device__ __align__(128) __half g_vj[(size_t)M_PAD * D_IN];
__device__ __align__(128) __half g_h1[(size_t)M_PAD * H1_DIM];
__device__ __align__(128) __half g_h2[(size_t)M_PAD * H2_DIM];
__device__ __align__(128) __half g_w1[(size_t)D_IN * H1_DIM];
__device__ __align__(128) __half g_w2[(size_t)H1_DIM * H2_DIM];
__device__ __align__(128) __half g_w3[(size_t)H2_DIM * O_DIM];

// ---------------- fp32 -> fp16 ----------------
__global__ void f2h_kernel(const float2* __restrict__ src,
                           __half2* __restrict__ dst, int n2) {
    int i = blockIdx.x * blockDim.x + threadIdx.x;
    int stride = gridDim.x * blockDim.x;
    for (; i < n2; i += stride) {
        float2 v = src[i];
        dst[i] = __floats2half2_rn(v.x, v.y);
    }
}

// ---------------- capsule mask ----------------
__global__ __launch_bounds__(256) void mask_kernel(const float* __restrict__ x,
                                                   __half* __restrict__ vj) {
    __shared__ float xs[64 * 168];
    __shared__ int bi[64];
    const int b0 = blockIdx.x * 64;

    const float4* src = (const float4*)(x + (size_t)b0 * D_IN);
    for (int q = threadIdx.x; q < 64 * 40; q += 256) {
        int s = q / 40, f = q % 40;
        *(float4*)&xs[s * 168 + f * 4] = src[q];
    }
    __syncthreads();

    if (threadIdx.x < 64) {
        const float* r = &xs[threadIdx.x * 168];
        float best = -1.f;
        int bidx = 0;
#pragma unroll
        for (int c = 0; c < N_CLASSES; c++) {
            float s = 0.f;
#pragma unroll
            for (int j = 0; j < UNIT; j++) {
                float v = r[c * UNIT + j];
                s += v * v;
            }
            if (s > best) { best = s; bidx = c; }
        }
        bi[threadIdx.x] = bidx;
    }
    __syncthreads();

    uint4* dst = (uint4*)(vj + (size_t)b0 * D_IN);
    for (int q = threadIdx.x; q < 64 * 20; q += 256) {
        int s = q / 20, j = q % 20;
        uint4 v = make_uint4(0u, 0u, 0u, 0u);
        int c = j >> 1;
        if (c == bi[s]) {
            const float* p = &xs[s * 168 + c * UNIT + (j & 1) * 8];
            __half2 h0 = __floats2half2_rn(p[0], p[1]);
            __half2 h1 = __floats2half2_rn(p[2], p[3]);
            __half2 h2 = __floats2half2_rn(p[4], p[5]);
            __half2 h3 = __floats2half2_rn(p[6], p[7]);
            v.x = *(uint32_t*)&h0; v.y = *(uint32_t*)&h1;
            v.z = *(uint32_t*)&h2; v.w = *(uint32_t*)&h3;
        }
        dst[q] = v;
    }
}

// ---------------- mma helpers ----------------
__device__ __forceinline__ void ldm_x4(uint32_t& r0, uint32_t& r1,
                                       uint32_t& r2, uint32_t& r3,
                                       uint32_t addr) {
    asm volatile("ldmatrix.sync.aligned.m8n8.x4.shared.b16 {%0,%1,%2,%3}, [%4];\n"
                 : "=r"(r0), "=r"(r1), "=r"(r2), "=r"(r3)
                 : "r"(addr));
}

__device__ __forceinline__ void ldm_x4_t(uint32_t& r0, uint32_t& r1,
                                         uint32_t& r2, uint32_t& r3,
                                         uint32_t addr) {
    asm volatile("ldmatrix.sync.aligned.m8n8.x4.trans.shared.b16 {%0,%1,%2,%3}, [%4];\n"
                 : "=r"(r0), "=r"(r1), "=r"(r2), "=r"(r3)
                 : "r"(addr));
}

__device__ __forceinline__ void mma_f16(uint32_t* c, const uint32_t* a,
                                        const uint32_t* b) {
    asm volatile(
        "mma.sync.aligned.m16n8k16.row.col.f16.f16.f16.f16 "
        "{%0,%1}, {%2,%3,%4,%5}, {%6,%7}, {%0,%1};\n"
        : "+r"(c[0]), "+r"(c[1])
        : "r"(a[0]), "r"(a[1]), "r"(a[2]), "r"(a[3]), "r"(b[0]), "r"(b[1]));
}

// ---------------- geometry ----------------
#define BK 32
#define A_LDS 40     // 32 + 8 pad (halves)
#define B_LDS 136    // 128 + 8 pad (halves)
#define STAGES 4
#define A_STG (TILE_M * A_LDS)     // 5440 halves
#define B_STG (BK * B_LDS)         // 4352 halves
#define SMEM_BYTES (STAGES * (A_STG + B_STG) * 2)   // 78336 B

#define NTHREADS 320   // 8 tensor warps + 2 fma warps

// A tile 136x32 (544 x 16B) + B tile 32x128 (512 x 16B)
__device__ __forceinline__ void ld_stage(uint32_t sA, uint32_t sB,
                                         const __half* __restrict__ A,
                                         const __half* __restrict__ Bm,
                                         int bm, int bn, int K, int N, int t,
                                         int tid) {
    const __half* Ag = A + (size_t)bm * K + t * BK;
    const __half* Bg = Bm + (size_t)t * BK * N + bn;
    {
        int q = tid;
        int r = q >> 2, c = (q & 3) * 8;
        asm volatile("cp.async.cg.shared.global [%0], [%1], 16;" ::
                     "r"(sA + (uint32_t)(r * A_LDS + c) * 2u),
                     "l"(Ag + (size_t)r * K + c));
        q = tid + NTHREADS;
        if (q < 544) {
            r = q >> 2; c = (q & 3) * 8;
            asm volatile("cp.async.cg.shared.global [%0], [%1], 16;" ::
                         "r"(sA + (uint32_t)(r * A_LDS + c) * 2u),
                         "l"(Ag + (size_t)r * K + c));
        }
    }
    {
        int q = tid;
        int r = q >> 4, c = (q & 15) * 8;
        asm volatile("cp.async.cg.shared.global [%0], [%1], 16;" ::
                     "r"(sB + (uint32_t)(r * B_LDS + c) * 2u),
                     "l"(Bg + (size_t)r * N + c));
        q = tid + NTHREADS;
        if (q < 512) {
            r = q >> 4; c = (q & 15) * 8;
            asm volatile("cp.async.cg.shared.global [%0], [%1], 16;" ::
                         "r"(sB + (uint32_t)(r * B_LDS + c) * 2u),
                         "l"(Bg + (size_t)r * N + c));
        }
    }
    asm volatile("cp.async.commit_group;" ::: "memory");
}

// ================= hybrid GEMM: tile 136x128 =================
// warps 0-7: tensor core rows [bm, bm+128) (proven R4 core, fp16 acc).
// warps 8-9: HFMA2 rows [bm+128, bm+136), 4 rows each, same B tile.
template <int ACT>
__global__ __launch_bounds__(NTHREADS, 2) void gemm_kernel(
    const __half* __restrict__ A,
    const __half* __restrict__ Bm,
    const float* __restrict__ bias,
    void* __restrict__ Cout,
    int N, int K) {
    extern __shared__ __half smem[];

    const int tid = threadIdx.x;
    const int warp = tid >> 5;
    const int lane = tid & 31;
    const int bm = blockIdx.y * TILE_M;
    const int bn = blockIdx.x * 128;

    const uint32_t sBase = (uint32_t)__cvta_generic_to_shared(smem);
    const uint32_t aBase = sBase;
    const uint32_t bBase = sBase + (uint32_t)STAGES * A_STG * 2u;

    const int T = K / BK;

    uint32_t tacc[4][4][2];
    float2 facc[4][2];

    const int warpM = warp >> 2;
    const int warpN = warp & 3;
    const int fw = warp - 8;

    if (warp < 8) {
#pragma unroll
        for (int mt = 0; mt < 4; mt++)
#pragma unroll
            for (int nt = 0; nt < 4; nt++) {
                tacc[mt][nt][0] = 0u;
                tacc[mt][nt][1] = 0u;
            }
    } else {
#pragma unroll
        for (int r = 0; r < 4; r++) {
            facc[r][0] = make_float2(0.f, 0.f);
            facc[r][1] = make_float2(0.f, 0.f);
        }
    }

#pragma unroll
    for (int t = 0; t < STAGES - 1; t++)
        ld_stage(aBase + (uint32_t)t * A_STG * 2u, bBase + (uint32_t)t * B_STG * 2u,
                 A, Bm, bm, bn, K, N, t, tid);

    for (int t = 0; t < T; t++) {
        asm volatile("cp.async.wait_group %0;" :: "n"(STAGES - 2) : "memory");
        __syncthreads();

        if (t + STAGES - 1 < T) {
            int sl = (t + STAGES - 1) & (STAGES - 1);
            ld_stage(aBase + (uint32_t)sl * A_STG * 2u,
                     bBase + (uint32_t)sl * B_STG * 2u,
                     A, Bm, bm, bn, K, N, t + STAGES - 1, tid);
        }

        const int s = t & (STAGES - 1);

        if (warp < 8) {
            const uint32_t sA = aBase + (uint32_t)s * A_STG * 2u;
            const uint32_t sB = bBase + (uint32_t)s * B_STG * 2u;
#pragma unroll
            for (int kk = 0; kk < BK; kk += 16) {
                uint32_t a[4][4];
#pragma unroll
                for (int mt = 0; mt < 4; mt++) {
                    int row = warpM * 64 + mt * 16 + (lane & 15);
                    int col = kk + ((lane >> 4) << 3);
                    ldm_x4(a[mt][0], a[mt][1], a[mt][2], a[mt][3],
                           sA + (uint32_t)(row * A_LDS + col) * 2u);
                }
                uint32_t b[4][2];
#pragma unroll
                for (int g = 0; g < 2; g++) {
                    int row = kk + (lane & 15);
                    int col = warpN * 32 + g * 16 + ((lane >> 4) << 3);
                    uint32_t r0, r1, r2, r3;
                    ldm_x4_t(r0, r1, r2, r3,
                             sB + (uint32_t)(row * B_LDS + col) * 2u);
                    b[2 * g][0] = r0; b[2 * g][1] = r1;
                    b[2 * g + 1][0] = r2; b[2 * g + 1][1] = r3;
                }
#pragma unroll
                for (int mt = 0; mt < 4; mt++)
#pragma unroll
                    for (int nt = 0; nt < 4; nt++)
                        mma_f16(tacc[mt][nt], a[mt], b[nt]);
            }
        } else {
            const __half* As = smem + (size_t)s * A_STG;
            const __half* Bs = smem + (size_t)STAGES * A_STG + (size_t)s * B_STG;
            const int rowb = 128 + fw * 4;
#pragma unroll
            for (int kc = 0; kc < BK; kc += 8) {
                uint4 a4[4];
#pragma unroll
                for (int r = 0; r < 4; r++)
                    a4[r] = *(const uint4*)&As[(rowb + r) * A_LDS + kc];
                __half2 ih[4][2];
#pragma unroll
                for (int r = 0; r < 4; r++) {
                    ih[r][0] = __floats2half2_rn(0.f, 0.f);
                    ih[r][1] = __floats2half2_rn(0.f, 0.f);
                }
#pragma unroll
                for (int kk = 0; kk < 8; kk++) {
                    uint2 b2 = *(const uint2*)&Bs[(kc + kk) * B_LDS + lane * 4];
                    __half2 b0 = *(__half2*)&b2.x;
                    __half2 b1 = *(__half2*)&b2.y;
#pragma unroll
                    for (int r = 0; r < 4; r++) {
                        __half av = ((const __half*)&a4[r])[kk];
                        __half2 av2 = __half2half2(av);
                        ih[r][0] = __hfma2(av2, b0, ih[r][0]);
                        ih[r][1] = __hfma2(av2, b1, ih[r][1]);
                    }
                }
#pragma unroll
                for (int r = 0; r < 4; r++) {
                    float2 f0 = __half22float2(ih[r][0]);
                    float2 f1 = __half22float2(ih[r][1]);
                    facc[r][0].x += f0.x; facc[r][0].y += f0.y;
                    facc[r][1].x += f1.x; facc[r][1].y += f1.y;
                }
            }
        }
        __syncthreads();
    }

    // ---------------- epilogues ----------------
    if (warp < 8) {
        const int lr = lane >> 2;
        const int lc = (lane & 3) * 2;
#pragma unroll
        for (int mt = 0; mt < 4; mt++) {
#pragma unroll
            for (int nt = 0; nt < 4; nt++) {
                int row0 = bm + warpM * 64 + mt * 16 + lr;
                int col = bn + warpN * 32 + nt * 8 + lc;
                float bz0 = __ldg(bias + col);
                float bz1 = __ldg(bias + col + 1);
                float2 p0 = __half22float2(*(__half2*)&tacc[mt][nt][0]);
                float2 p1 = __half22float2(*(__half2*)&tacc[mt][nt][1]);
                float v00 = p0.x + bz0;
                float v01 = p0.y + bz1;
                float v10 = p1.x + bz0;
                float v11 = p1.y + bz1;
                if (ACT == 0) {
                    v00 = fmaxf(v00, 0.f); v01 = fmaxf(v01, 0.f);
                    v10 = fmaxf(v10, 0.f); v11 = fmaxf(v11, 0.f);
                    __half* C = (__half*)Cout;
                    *(__half2*)&C[(size_t)row0 * N + col] =
                        __floats2half2_rn(v00, v01);
                    *(__half2*)&C[(size_t)(row0 + 8) * N + col] =
                        __floats2half2_rn(v10, v11);
                } else {
                    v00 = 1.f / (1.f + __expf(-v00));
                    v01 = 1.f / (1.f + __expf(-v01));
                    v10 = 1.f / (1.f + __expf(-v10));
                    v11 = 1.f / (1.f + __expf(-v11));
                    float* C = (float*)Cout;
                    *(float2*)&C[(size_t)row0 * N + col] = make_float2(v00, v01);
                    *(float2*)&C[(size_t)(row0 + 8) * N + col] = make_float2(v10, v11);
                }
            }
        }
    } else {
        const int col = bn + lane * 4;
        float4 bz = __ldg((const float4*)(bias + col));
#pragma unroll
        for (int r = 0; r < 4; r++) {
            int row = bm + 128 + fw * 4 + r;
            if (row >= B_SAMPLES) continue;
            float v0 = facc[r][0].x + bz.x;
            float v1 = facc[r][0].y + bz.y;
            float v2 = facc[r][1].x + bz.z;
            float v3 = facc[r][1].y + bz.w;
            if (ACT == 0) {
                v0 = fmaxf(v0, 0.f); v1 = fmaxf(v1, 0.f);
                v2 = fmaxf(v2, 0.f); v3 = fmaxf(v3, 0.f);
                __half* C = (__half*)Cout;
                __half2 h0 = __floats2half2_rn(v0, v1);
                __half2 h1 = __floats2half2_rn(v2, v3);
                uint2 pk;
                pk.x = *(uint32_t*)&h0;
                pk.y = *(uint32_t*)&h1;
                *(uint2*)&C[(size_t)row * N + col] = pk;
            } else {
                v0 = 1.f / (1.f + __expf(-v0));
                v1 = 1.f / (1.f + __expf(-v1));
                v2 = 1.f / (1.f + __expf(-v2));
                v3 = 1.f / (1.f + __expf(-v3));
                float* C = (float*)Cout;
                *(float4*)&C[(size_t)row * N + col] = make_float4(v0, v1, v2, v3);
            }
        }
    }
}

// ---------------- launch ----------------
extern "C" void kernel_launch(void* const* d_in, const int* in_sizes, int n_in,
                              void* d_out, int out_size) {
    const float* x  = (const float*)d_in[0];
    const float* W1 = (const float*)d_in[2];
    const float* b1 = (const float*)d_in[3];
    const float* W2 = (const float*)d_in[4];
    const float* b2 = (const float*)d_in[5];
    const float* W3 = (const float*)d_in[6];
    const float* b3 = (const float*)d_in[7];

    void *pvj, *ph1, *ph2, *pw1, *pw2, *pw3;
    cudaGetSymbolAddress(&pvj, g_vj);
    cudaGetSymbolAddress(&ph1, g_h1);
    cudaGetSymbolAddress(&ph2, g_h2);
    cudaGetSymbolAddress(&pw1, g_w1);
    cudaGetSymbolAddress(&pw2, g_w2);
    cudaGetSymbolAddress(&pw3, g_w3);
    __half* vj  = (__half*)pvj;
    __half* h1  = (__half*)ph1;
    __half* h2  = (__half*)ph2;
    __half* w1h = (__half*)pw1;
    __half* w2h = (__half*)pw2;
    __half* w3h = (__half*)pw3;

    cudaFuncSetAttribute(gemm_kernel<0>,
                         cudaFuncAttributeMaxDynamicSharedMemorySize, SMEM_BYTES);
    cudaFuncSetAttribute(gemm_kernel<1>,
                         cudaFuncAttributeMaxDynamicSharedMemorySize, SMEM_BYTES);

    f2h_kernel<<<128, 256>>>((const float2*)W1, (__half2*)w1h,
                             D_IN * H1_DIM / 2);
    f2h_kernel<<<256, 256>>>((const float2*)W2, (__half2*)w2h,
                             H1_DIM * H2_DIM / 2);
    f2h_kernel<<<512, 256>>>((const float2*)W3, (__half2*)w3h,
                             H2_DIM * O_DIM / 2);

    mask_kernel<<<B_SAMPLES / 64, 256>>>(x, vj);

    gemm_kernel<0><<<dim3(H1_DIM / 128, GRID_Y), NTHREADS, SMEM_BYTES>>>(
        vj, w1h, b1, h1, H1_DIM, D_IN);
    gemm_kernel<0><<<dim3(H2_DIM / 128, GRID_Y), NTHREADS, SMEM_BYTES>>>(
        h1, w2h, b2, h2, H2_DIM, H1_DIM);
    gemm_kernel<1><<<dim3(O_DIM / 128, GRID_Y), NTHREADS, SMEM_BYTES>>>(
        h2, w3h, b3, d_out, O_DIM, H2_DIM);
}

// round 9
// speedup vs baseline: 2.0252x; 1.4492x over previous
#include <cuda_runtime.h>
#include <cuda_bf16.h>
#include <cstdint>

#define B_SAMPLES 32768
#define N_CLASSES 10
#define UNIT 16
#define D_IN 160
#define D_IN_PAD 192
#define H1_DIM 512
#define H2_DIM 1024
#define O_DIM 3072

// ---------------- scratch ----------------
__device__ __align__(128) __nv_bfloat16 g_vj[(size_t)B_SAMPLES * D_IN_PAD];
__device__ __align__(128) __nv_bfloat16 g_h1[(size_t)B_SAMPLES * H1_DIM];
__device__ __align__(128) __nv_bfloat16 g_h2[(size_t)B_SAMPLES * H2_DIM];
__device__ __align__(128) __nv_bfloat16 g_w1[(size_t)D_IN * H1_DIM];
__device__ __align__(128) __nv_bfloat16 g_w2[(size_t)H1_DIM * H2_DIM];
__device__ __align__(128) __nv_bfloat16 g_w3[(size_t)H2_DIM * O_DIM];

#define W1_N2 (D_IN * H1_DIM / 2)
#define W2_N2 (H1_DIM * H2_DIM / 2)
#define W3_N2 (H2_DIM * O_DIM / 2)

// ---------------- merged fp32 -> bf16 for all three weights ----------------
__global__ void f2bf_all(const float2* __restrict__ w1,
                         const float2* __restrict__ w2,
                         const float2* __restrict__ w3,
                         __nv_bfloat162* __restrict__ o1,
                         __nv_bfloat162* __restrict__ o2,
                         __nv_bfloat162* __restrict__ o3) {
    const int total = W1_N2 + W2_N2 + W3_N2;
    int i = blockIdx.x * blockDim.x + threadIdx.x;
    int stride = gridDim.x * blockDim.x;
    for (; i < total; i += stride) {
        float2 v;
        __nv_bfloat162* dst;
        if (i < W1_N2) {
            v = w1[i];
            dst = o1 + i;
        } else if (i < W1_N2 + W2_N2) {
            v = w2[i - W1_N2];
            dst = o2 + (i - W1_N2);
        } else {
            v = w3[i - W1_N2 - W2_N2];
            dst = o3 + (i - W1_N2 - W2_N2);
        }
        *dst = __floats2bfloat162_rn(v.x, v.y);
    }
}

// ---------------- capsule mask -> vj padded to 192 cols ---------------------
__global__ __launch_bounds__(256) void mask_kernel(const float* __restrict__ x,
                                                   __nv_bfloat16* __restrict__ vj) {
    __shared__ float xs[64 * 168];
    __shared__ int bi[64];
    const int b0 = blockIdx.x * 64;

    const float4* src = (const float4*)(x + (size_t)b0 * D_IN);
    for (int q = threadIdx.x; q < 64 * 40; q += 256) {
        int s = q / 40, f = q % 40;
        *(float4*)&xs[s * 168 + f * 4] = src[q];
    }
    __syncthreads();

    if (threadIdx.x < 64) {
        const float* r = &xs[threadIdx.x * 168];
        float best = -1.f;
        int bidx = 0;
#pragma unroll
        for (int c = 0; c < N_CLASSES; c++) {
            float s = 0.f;
#pragma unroll
            for (int j = 0; j < UNIT; j++) {
                float v = r[c * UNIT + j];
                s += v * v;
            }
            if (s > best) { best = s; bidx = c; }
        }
        bi[threadIdx.x] = bidx;
    }
    __syncthreads();

    uint4* dst = (uint4*)(vj + (size_t)b0 * D_IN_PAD);
    for (int q = threadIdx.x; q < 64 * 24; q += 256) {
        int s = q / 24, j = q % 24;
        uint4 v = make_uint4(0u, 0u, 0u, 0u);
        int c = j >> 1;
        if (j < 20 && c == bi[s]) {
            const float* p = &xs[s * 168 + c * UNIT + (j & 1) * 8];
            __nv_bfloat162 h0 = __floats2bfloat162_rn(p[0], p[1]);
            __nv_bfloat162 h1 = __floats2bfloat162_rn(p[2], p[3]);
            __nv_bfloat162 h2 = __floats2bfloat162_rn(p[4], p[5]);
            __nv_bfloat162 h3 = __floats2bfloat162_rn(p[6], p[7]);
            v.x = *(uint32_t*)&h0; v.y = *(uint32_t*)&h1;
            v.z = *(uint32_t*)&h2; v.w = *(uint32_t*)&h3;
        }
        dst[q] = v;
    }
}

// ---------------- mma helpers ----------------
__device__ __forceinline__ void ldm_x4(uint32_t& r0, uint32_t& r1,
                                       uint32_t& r2, uint32_t& r3,
                                       uint32_t addr) {
    asm volatile("ldmatrix.sync.aligned.m8n8.x4.shared.b16 {%0,%1,%2,%3}, [%4];\n"
                 : "=r"(r0), "=r"(r1), "=r"(r2), "=r"(r3)
                 : "r"(addr));
}

__device__ __forceinline__ void ldm_x4_t(uint32_t& r0, uint32_t& r1,
                                         uint32_t& r2, uint32_t& r3,
                                         uint32_t addr) {
    asm volatile("ldmatrix.sync.aligned.m8n8.x4.trans.shared.b16 {%0,%1,%2,%3}, [%4];\n"
                 : "=r"(r0), "=r"(r1), "=r"(r2), "=r"(r3)
                 : "r"(addr));
}

__device__ __forceinline__ void mma_bf16(float* c, const uint32_t* a,
                                         const uint32_t* b) {
    asm volatile(
        "mma.sync.aligned.m16n8k16.row.col.f32.bf16.bf16.f32 "
        "{%0,%1,%2,%3}, {%4,%5,%6,%7}, {%8,%9}, {%0,%1,%2,%3};\n"
        : "+f"(c[0]), "+f"(c[1]), "+f"(c[2]), "+f"(c[3])
        : "r"(a[0]), "r"(a[1]), "r"(a[2]), "r"(a[3]), "r"(b[0]), "r"(b[1]));
}

// ---------------- geometry: BK=64, 3 stages ----------------
#define BK 64
#define A_LDS 72    // 64 + 8 pad (halves)
#define B_LDS 136   // 128 + 8 pad (halves)
#define STAGES 3
#define A_STG (128 * A_LDS)          // 9216 halves
#define B_STG (BK * B_LDS)           // 8704 halves
#define SMEM_BYTES (STAGES * (A_STG + B_STG) * 2)   // 107520 B

// A tile 128x64 (1024 x 16B), B tile 64x128 (1024 x 16B); 256 threads, 4 each
__device__ __forceinline__ void ld_stage(uint32_t sA, uint32_t sB,
                                         const __nv_bfloat16* __restrict__ A,
                                         const __nv_bfloat16* __restrict__ Bm,
                                         int bm, int bn, int K, int N, int t,
                                         int tid) {
    const __nv_bfloat16* Ag = A + (size_t)bm * K + t * BK;
    const __nv_bfloat16* Bg = Bm + (size_t)t * BK * N + bn;
#pragma unroll
    for (int i = 0; i < 4; i++) {
        int q = tid + i * 256;
        int ar = q >> 3, ac = (q & 7) * 8;
        asm volatile("cp.async.cg.shared.global [%0], [%1], 16;" ::
                     "r"(sA + (uint32_t)(ar * A_LDS + ac) * 2u),
                     "l"(Ag + (size_t)ar * K + ac));
        int br = q >> 4, bc = (q & 15) * 8;
        asm volatile("cp.async.cg.shared.global [%0], [%1], 16;" ::
                     "r"(sB + (uint32_t)(br * B_LDS + bc) * 2u),
                     "l"(Bg + (size_t)br * N + bc));
    }
    asm volatile("cp.async.commit_group;" ::: "memory");
}

// ================= GEMM: C = act(A[M,K] @ B[K,N] + bias) =================
// BM=128, BN=128, BK=64, 3-stage cp.async pipeline, 256 thr (8 warps 2x4).
template <int ACT>
__global__ __launch_bounds__(256, 2) void gemm_kernel(
    const __nv_bfloat16* __restrict__ A,
    const __nv_bfloat16* __restrict__ Bm,
    const float* __restrict__ bias,
    void* __restrict__ Cout,
    int N, int K) {
    extern __shared__ __nv_bfloat16 smem[];

    const int tid = threadIdx.x;
    const int warp = tid >> 5;
    const int lane = tid & 31;
    const int warpM = warp >> 2;
    const int warpN = warp & 3;
    const int bm = blockIdx.y * 128;
    const int bn = blockIdx.x * 128;

    const uint32_t sBase = (uint32_t)__cvta_generic_to_shared(smem);
    const uint32_t aBase = sBase;
    const uint32_t bBase = sBase + (uint32_t)STAGES * A_STG * 2u;

    float acc[4][4][4];
#pragma unroll
    for (int mt = 0; mt < 4; mt++)
#pragma unroll
        for (int nt = 0; nt < 4; nt++)
#pragma unroll
            for (int r = 0; r < 4; r++) acc[mt][nt][r] = 0.f;

    const int T = K / BK;

    // prologue: prefetch 2 stages into slots 0,1
    ld_stage(aBase, bBase, A, Bm, bm, bn, K, N, 0, tid);
    if (T > 1)
        ld_stage(aBase + (uint32_t)A_STG * 2u, bBase + (uint32_t)B_STG * 2u,
                 A, Bm, bm, bn, K, N, 1, tid);
    else
        asm volatile("cp.async.commit_group;" ::: "memory");

    int s = 0;       // current compute slot
    int sl = 2;      // next load slot
    for (int t = 0; t < T; t++) {
        asm volatile("cp.async.wait_group 1;" ::: "memory");
        __syncthreads();

        if (t + 2 < T) {
            ld_stage(aBase + (uint32_t)sl * A_STG * 2u,
                     bBase + (uint32_t)sl * B_STG * 2u,
                     A, Bm, bm, bn, K, N, t + 2, tid);
        } else {
            asm volatile("cp.async.commit_group;" ::: "memory");
        }
        sl = (sl + 1 == STAGES) ? 0 : sl + 1;

        const uint32_t sA = aBase + (uint32_t)s * A_STG * 2u;
        const uint32_t sB = bBase + (uint32_t)s * B_STG * 2u;
        s = (s + 1 == STAGES) ? 0 : s + 1;

#pragma unroll
        for (int kk = 0; kk < BK; kk += 16) {
            uint32_t a[4][4];
#pragma unroll
            for (int mt = 0; mt < 4; mt++) {
                int row = warpM * 64 + mt * 16 + (lane & 15);
                int col = kk + ((lane >> 4) << 3);
                ldm_x4(a[mt][0], a[mt][1], a[mt][2], a[mt][3],
                       sA + (uint32_t)(row * A_LDS + col) * 2u);
            }
            uint32_t b[4][2];
#pragma unroll
            for (int g = 0; g < 2; g++) {
                int row = kk + (lane & 15);
                int col = warpN * 32 + g * 16 + ((lane >> 4) << 3);
                uint32_t r0, r1, r2, r3;
                ldm_x4_t(r0, r1, r2, r3, sB + (uint32_t)(row * B_LDS + col) * 2u);
                b[2 * g][0] = r0; b[2 * g][1] = r1;
                b[2 * g + 1][0] = r2; b[2 * g + 1][1] = r3;
            }
#pragma unroll
            for (int mt = 0; mt < 4; mt++)
#pragma unroll
                for (int nt = 0; nt < 4; nt++)
                    mma_bf16(acc[mt][nt], a[mt], b[nt]);
        }
        __syncthreads();
    }

    // epilogue
    const int lr = lane >> 2;
    const int lc = (lane & 3) * 2;
#pragma unroll
    for (int mt = 0; mt < 4; mt++) {
#pragma unroll
        for (int nt = 0; nt < 4; nt++) {
            int row0 = bm + warpM * 64 + mt * 16 + lr;
            int col = bn + warpN * 32 + nt * 8 + lc;
            float bz0 = __ldg(bias + col);
            float bz1 = __ldg(bias + col + 1);
            float v00 = acc[mt][nt][0] + bz0;
            float v01 = acc[mt][nt][1] + bz1;
            float v10 = acc[mt][nt][2] + bz0;
            float v11 = acc[mt][nt][3] + bz1;
            if (ACT == 0) {
                v00 = fmaxf(v00, 0.f); v01 = fmaxf(v01, 0.f);
                v10 = fmaxf(v10, 0.f); v11 = fmaxf(v11, 0.f);
                __nv_bfloat16* C = (__nv_bfloat16*)Cout;
                *(__nv_bfloat162*)&C[(size_t)row0 * N + col] =
                    __floats2bfloat162_rn(v00, v01);
                *(__nv_bfloat162*)&C[(size_t)(row0 + 8) * N + col] =
                    __floats2bfloat162_rn(v10, v11);
            } else {
                v00 = 1.f / (1.f + __expf(-v00));
                v01 = 1.f / (1.f + __expf(-v01));
                v10 = 1.f / (1.f + __expf(-v10));
                v11 = 1.f / (1.f + __expf(-v11));
                float* C = (float*)Cout;
                *(float2*)&C[(size_t)row0 * N + col] = make_float2(v00, v01);
                *(float2*)&C[(size_t)(row0 + 8) * N + col] = make_float2(v10, v11);
            }
        }
    }
}

// ---------------- launch ----------------
extern "C" void kernel_launch(void* const* d_in, const int* in_sizes, int n_in,
                              void* d_out, int out_size) {
    const float* x  = (const float*)d_in[0];
    const float* W1 = (const float*)d_in[2];
    const float* b1 = (const float*)d_in[3];
    const float* W2 = (const float*)d_in[4];
    const float* b2 = (const float*)d_in[5];
    const float* W3 = (const float*)d_in[6];
    const float* b3 = (const float*)d_in[7];

    void *pvj, *ph1, *ph2, *pw1, *pw2, *pw3;
    cudaGetSymbolAddress(&pvj, g_vj);
    cudaGetSymbolAddress(&ph1, g_h1);
    cudaGetSymbolAddress(&ph2, g_h2);
    cudaGetSymbolAddress(&pw1, g_w1);
    cudaGetSymbolAddress(&pw2, g_w2);
    cudaGetSymbolAddress(&pw3, g_w3);
    __nv_bfloat16* vj  = (__nv_bfloat16*)pvj;
    __nv_bfloat16* h1  = (__nv_bfloat16*)ph1;
    __nv_bfloat16* h2  = (__nv_bfloat16*)ph2;
    __nv_bfloat16* w1b = (__nv_bfloat16*)pw1;
    __nv_bfloat16* w2b = (__nv_bfloat16*)pw2;
    __nv_bfloat16* w3b = (__nv_bfloat16*)pw3;

    cudaFuncSetAttribute(gemm_kernel<0>,
                         cudaFuncAttributeMaxDynamicSharedMemorySize, SMEM_BYTES);
    cudaFuncSetAttribute(gemm_kernel<1>,
                         cudaFuncAttributeMaxDynamicSharedMemorySize, SMEM_BYTES);

    // one conversion kernel for all weights
    f2bf_all<<<592, 256>>>((const float2*)W1, (const float2*)W2,
                           (const float2*)W3, (__nv_bfloat162*)w1b,
                           (__nv_bfloat162*)w2b, (__nv_bfloat162*)w3b);

    // capsule mask -> vj [B, 192] (cols 160..191 zero)
    mask_kernel<<<B_SAMPLES / 64, 256>>>(x, vj);

    gemm_kernel<0><<<dim3(H1_DIM / 128, B_SAMPLES / 128), 256, SMEM_BYTES>>>(
        vj, w1b, b1, h1, H1_DIM, D_IN_PAD);
    gemm_kernel<0><<<dim3(H2_DIM / 128, B_SAMPLES / 128), 256, SMEM_BYTES>>>(
        h1, w2b, b2, h2, H2_DIM, H1_DIM);
    gemm_kernel<1><<<dim3(O_DIM / 128, B_SAMPLES / 128), 256, SMEM_BYTES>>>(
        h2, w3b, b3, d_out, O_DIM, H2_DIM);
}

// round 10
// speedup vs baseline: 2.0879x; 1.0310x over previous
#include <cuda_runtime.h>
#include <cuda_fp16.h>
#include <cstdint>

#define B_SAMPLES 32768
#define N_CLASSES 10
#define UNIT 16
#define D_IN 160
#define D_IN_PAD 192
#define H1_DIM 512
#define H2_DIM 1024
#define O_DIM 3072

// ---------------- scratch ----------------
__device__ __align__(128) __half g_vj[(size_t)B_SAMPLES * D_IN_PAD];
__device__ __align__(128) __half g_h1[(size_t)B_SAMPLES * H1_DIM];
__device__ __align__(128) __half g_h2[(size_t)B_SAMPLES * H2_DIM];
__device__ __align__(128) __half g_w1[(size_t)D_IN * H1_DIM];
__device__ __align__(128) __half g_w2[(size_t)H1_DIM * H2_DIM];
__device__ __align__(128) __half g_w3[(size_t)H2_DIM * O_DIM];

#define W1_N2 (D_IN * H1_DIM / 2)
#define W2_N2 (H1_DIM * H2_DIM / 2)
#define W3_N2 (H2_DIM * O_DIM / 2)

// ---------------- merged fp32 -> fp16 for all three weights ----------------
__global__ void f2h_all(const float2* __restrict__ w1,
                        const float2* __restrict__ w2,
                        const float2* __restrict__ w3,
                        __half2* __restrict__ o1,
                        __half2* __restrict__ o2,
                        __half2* __restrict__ o3) {
    const int total = W1_N2 + W2_N2 + W3_N2;
    int i = blockIdx.x * blockDim.x + threadIdx.x;
    int stride = gridDim.x * blockDim.x;
    for (; i < total; i += stride) {
        float2 v;
        __half2* dst;
        if (i < W1_N2) {
            v = w1[i];
            dst = o1 + i;
        } else if (i < W1_N2 + W2_N2) {
            v = w2[i - W1_N2];
            dst = o2 + (i - W1_N2);
        } else {
            v = w3[i - W1_N2 - W2_N2];
            dst = o3 + (i - W1_N2 - W2_N2);
        }
        *dst = __floats2half2_rn(v.x, v.y);
    }
}

// ---------------- capsule mask -> vj padded to 192 cols ---------------------
__global__ __launch_bounds__(256) void mask_kernel(const float* __restrict__ x,
                                                   __half* __restrict__ vj) {
    __shared__ float xs[64 * 168];
    __shared__ int bi[64];
    const int b0 = blockIdx.x * 64;

    const float4* src = (const float4*)(x + (size_t)b0 * D_IN);
    for (int q = threadIdx.x; q < 64 * 40; q += 256) {
        int s = q / 40, f = q % 40;
        *(float4*)&xs[s * 168 + f * 4] = src[q];
    }
    __syncthreads();

    if (threadIdx.x < 64) {
        const float* r = &xs[threadIdx.x * 168];
        float best = -1.f;
        int bidx = 0;
#pragma unroll
        for (int c = 0; c < N_CLASSES; c++) {
            float s = 0.f;
#pragma unroll
            for (int j = 0; j < UNIT; j++) {
                float v = r[c * UNIT + j];
                s += v * v;
            }
            if (s > best) { best = s; bidx = c; }
        }
        bi[threadIdx.x] = bidx;
    }
    __syncthreads();

    uint4* dst = (uint4*)(vj + (size_t)b0 * D_IN_PAD);
    for (int q = threadIdx.x; q < 64 * 24; q += 256) {
        int s = q / 24, j = q % 24;
        uint4 v = make_uint4(0u, 0u, 0u, 0u);
        int c = j >> 1;
        if (j < 20 && c == bi[s]) {
            const float* p = &xs[s * 168 + c * UNIT + (j & 1) * 8];
            __half2 h0 = __floats2half2_rn(p[0], p[1]);
            __half2 h1 = __floats2half2_rn(p[2], p[3]);
            __half2 h2 = __floats2half2_rn(p[4], p[5]);
            __half2 h3 = __floats2half2_rn(p[6], p[7]);
            v.x = *(uint32_t*)&h0; v.y = *(uint32_t*)&h1;
            v.z = *(uint32_t*)&h2; v.w = *(uint32_t*)&h3;
        }
        dst[q] = v;
    }
}

// ---------------- mma helpers ----------------
__device__ __forceinline__ void ldm_x4(uint32_t& r0, uint32_t& r1,
                                       uint32_t& r2, uint32_t& r3,
                                       uint32_t addr) {
    asm volatile("ldmatrix.sync.aligned.m8n8.x4.shared.b16 {%0,%1,%2,%3}, [%4];\n"
                 : "=r"(r0), "=r"(r1), "=r"(r2), "=r"(r3)
                 : "r"(addr));
}

__device__ __forceinline__ void ldm_x4_t(uint32_t& r0, uint32_t& r1,
                                         uint32_t& r2, uint32_t& r3,
                                         uint32_t addr) {
    asm volatile("ldmatrix.sync.aligned.m8n8.x4.trans.shared.b16 {%0,%1,%2,%3}, [%4];\n"
                 : "=r"(r0), "=r"(r1), "=r"(r2), "=r"(r3)
                 : "r"(addr));
}

// fp16 accumulate HMMA
__device__ __forceinline__ void mma_f16(uint32_t* c, const uint32_t* a,
                                        const uint32_t* b) {
    asm volatile(
        "mma.sync.aligned.m16n8k16.row.col.f16.f16.f16.f16 "
        "{%0,%1}, {%2,%3,%4,%5}, {%6,%7}, {%0,%1};\n"
        : "+r"(c[0]), "+r"(c[1])
        : "r"(a[0]), "r"(a[1]), "r"(a[2]), "r"(a[3]), "r"(b[0]), "r"(b[1]));
}

// ---------------- geometry: BM=128, BN=256, BK=64, 2 stages ----------------
#define BK 64
#define A_LDS 72     // 64 + 8 (halves)
#define B_LDS 264    // 256 + 8 (halves)
#define STAGES 2
#define A_STG (128 * A_LDS)          // 9216 halves
#define B_STG (BK * B_LDS)           // 16896 halves
#define SMEM_BYTES (STAGES * (A_STG + B_STG) * 2)   // 104448 B

// A tile 128x64 (1024 x 16B), B tile 64x256 (2048 x 16B), 256 threads
__device__ __forceinline__ void ld_stage(uint32_t sA, uint32_t sB,
                                         const __half* __restrict__ A,
                                         const __half* __restrict__ Bm,
                                         int bm, int bn, int K, int N, int t,
                                         int tid) {
    const __half* Ag = A + (size_t)bm * K + t * BK;
    const __half* Bg = Bm + (size_t)t * BK * N + bn;
#pragma unroll
    for (int i = 0; i < 4; i++) {
        int q = tid + i * 256;
        int ar = q >> 3, ac = (q & 7) * 8;
        asm volatile("cp.async.cg.shared.global [%0], [%1], 16;" ::
                     "r"(sA + (uint32_t)(ar * A_LDS + ac) * 2u),
                     "l"(Ag + (size_t)ar * K + ac));
    }
#pragma unroll
    for (int i = 0; i < 8; i++) {
        int q = tid + i * 256;
        int br = q >> 5, bc = (q & 31) * 8;
        asm volatile("cp.async.cg.shared.global [%0], [%1], 16;" ::
                     "r"(sB + (uint32_t)(br * B_LDS + bc) * 2u),
                     "l"(Bg + (size_t)br * N + bc));
    }
    asm volatile("cp.async.commit_group;" ::: "memory");
}

// ================= GEMM: tile 128x256, warp tile 64x64 =================
// 8 warps (2 warpM x 4 warpN). fp16 accumulation.
template <int ACT>
__global__ __launch_bounds__(256, 2) void gemm_kernel(
    const __half* __restrict__ A,
    const __half* __restrict__ Bm,
    const float* __restrict__ bias,
    void* __restrict__ Cout,
    int N, int K) {
    extern __shared__ __half smem[];

    const int tid = threadIdx.x;
    const int warp = tid >> 5;
    const int lane = tid & 31;
    const int warpM = warp >> 2;
    const int warpN = warp & 3;
    const int bm = blockIdx.y * 128;
    const int bn = blockIdx.x * 256;

    const uint32_t sBase = (uint32_t)__cvta_generic_to_shared(smem);
    const uint32_t aBase = sBase;
    const uint32_t bBase = sBase + (uint32_t)STAGES * A_STG * 2u;

    uint32_t acc[4][8][2];
#pragma unroll
    for (int mt = 0; mt < 4; mt++)
#pragma unroll
        for (int n8 = 0; n8 < 8; n8++) {
            acc[mt][n8][0] = 0u;
            acc[mt][n8][1] = 0u;
        }

    const int T = K / BK;

    ld_stage(aBase, bBase, A, Bm, bm, bn, K, N, 0, tid);

    for (int t = 0; t < T; t++) {
        if (t + 1 < T) {
            int sl = (t + 1) & 1;
            ld_stage(aBase + (uint32_t)sl * A_STG * 2u,
                     bBase + (uint32_t)sl * B_STG * 2u,
                     A, Bm, bm, bn, K, N, t + 1, tid);
        } else {
            asm volatile("cp.async.commit_group;" ::: "memory");
        }
        asm volatile("cp.async.wait_group 1;" ::: "memory");
        __syncthreads();

        const int s = t & 1;
        const uint32_t sA = aBase + (uint32_t)s * A_STG * 2u;
        const uint32_t sB = bBase + (uint32_t)s * B_STG * 2u;

#pragma unroll
        for (int kk = 0; kk < BK; kk += 16) {
            uint32_t a[4][4];
#pragma unroll
            for (int mt = 0; mt < 4; mt++) {
                int row = warpM * 64 + mt * 16 + (lane & 15);
                int col = kk + ((lane >> 4) << 3);
                ldm_x4(a[mt][0], a[mt][1], a[mt][2], a[mt][3],
                       sA + (uint32_t)(row * A_LDS + col) * 2u);
            }
            uint32_t b[8][2];
#pragma unroll
            for (int nt = 0; nt < 4; nt++) {
                int row = kk + (lane & 15);
                int col = warpN * 64 + nt * 16 + ((lane >> 4) << 3);
                uint32_t r0, r1, r2, r3;
                ldm_x4_t(r0, r1, r2, r3, sB + (uint32_t)(row * B_LDS + col) * 2u);
                b[2 * nt][0] = r0; b[2 * nt][1] = r1;
                b[2 * nt + 1][0] = r2; b[2 * nt + 1][1] = r3;
            }
#pragma unroll
            for (int mt = 0; mt < 4; mt++)
#pragma unroll
                for (int n8 = 0; n8 < 8; n8++)
                    mma_f16(acc[mt][n8], a[mt], b[n8]);
        }
        __syncthreads();
    }

    // epilogue
    const int lr = lane >> 2;
    const int lc = (lane & 3) * 2;
#pragma unroll
    for (int mt = 0; mt < 4; mt++) {
#pragma unroll
        for (int n8 = 0; n8 < 8; n8++) {
            int row0 = bm + warpM * 64 + mt * 16 + lr;
            int col = bn + warpN * 64 + n8 * 8 + lc;
            float bz0 = __ldg(bias + col);
            float bz1 = __ldg(bias + col + 1);
            float2 p0 = __half22float2(*(__half2*)&acc[mt][n8][0]);
            float2 p1 = __half22float2(*(__half2*)&acc[mt][n8][1]);
            float v00 = p0.x + bz0;
            float v01 = p0.y + bz1;
            float v10 = p1.x + bz0;
            float v11 = p1.y + bz1;
            if (ACT == 0) {
                v00 = fmaxf(v00, 0.f); v01 = fmaxf(v01, 0.f);
                v10 = fmaxf(v10, 0.f); v11 = fmaxf(v11, 0.f);
                __half* C = (__half*)Cout;
                *(__half2*)&C[(size_t)row0 * N + col] = __floats2half2_rn(v00, v01);
                *(__half2*)&C[(size_t)(row0 + 8) * N + col] = __floats2half2_rn(v10, v11);
            } else {
                v00 = 1.f / (1.f + __expf(-v00));
                v01 = 1.f / (1.f + __expf(-v01));
                v10 = 1.f / (1.f + __expf(-v10));
                v11 = 1.f / (1.f + __expf(-v11));
                float* C = (float*)Cout;
                *(float2*)&C[(size_t)row0 * N + col] = make_float2(v00, v01);
                *(float2*)&C[(size_t)(row0 + 8) * N + col] = make_float2(v10, v11);
            }
        }
    }
}

// ---------------- launch ----------------
extern "C" void kernel_launch(void* const* d_in, const int* in_sizes, int n_in,
                              void* d_out, int out_size) {
    const float* x  = (const float*)d_in[0];
    const float* W1 = (const float*)d_in[2];
    const float* b1 = (const float*)d_in[3];
    const float* W2 = (const float*)d_in[4];
    const float* b2 = (const float*)d_in[5];
    const float* W3 = (const float*)d_in[6];
    const float* b3 = (const float*)d_in[7];

    void *pvj, *ph1, *ph2, *pw1, *pw2, *pw3;
    cudaGetSymbolAddress(&pvj, g_vj);
    cudaGetSymbolAddress(&ph1, g_h1);
    cudaGetSymbolAddress(&ph2, g_h2);
    cudaGetSymbolAddress(&pw1, g_w1);
    cudaGetSymbolAddress(&pw2, g_w2);
    cudaGetSymbolAddress(&pw3, g_w3);
    __half* vj  = (__half*)pvj;
    __half* h1  = (__half*)ph1;
    __half* h2  = (__half*)ph2;
    __half* w1h = (__half*)pw1;
    __half* w2h = (__half*)pw2;
    __half* w3h = (__half*)pw3;

    cudaFuncSetAttribute(gemm_kernel<0>,
                         cudaFuncAttributeMaxDynamicSharedMemorySize, SMEM_BYTES);
    cudaFuncSetAttribute(gemm_kernel<1>,
                         cudaFuncAttributeMaxDynamicSharedMemorySize, SMEM_BYTES);

    f2h_all<<<592, 256>>>((const float2*)W1, (const float2*)W2,
                          (const float2*)W3, (__half2*)w1h,
                          (__half2*)w2h, (__half2*)w3h);

    mask_kernel<<<B_SAMPLES / 64, 256>>>(x, vj);

    gemm_kernel<0><<<dim3(H1_DIM / 256, B_SAMPLES / 128), 256, SMEM_BYTES>>>(
        vj, w1h, b1, h1, H1_DIM, D_IN_PAD);
    gemm_kernel<0><<<dim3(H2_DIM / 256, B_SAMPLES / 128), 256, SMEM_BYTES>>>(
        h1, w2h, b2, h2, H2_DIM, H1_DIM);
    gemm_kernel<1><<<dim3(O_DIM / 256, B_SAMPLES / 128), 256, SMEM_BYTES>>>(
        h2, w3h, b3, d_out, O_DIM, H2_DIM);
}